// round 15
// baseline (speedup 1.0000x reference)
#include <cuda_runtime.h>
#include <math.h>

#define TT 6
#define NN 50000
#define EE 800000
#define FF 32
#define HH 64
#define OUTC 16

#define TOTN (TT * NN)                 // 300000
#define SCAN_T_BLOCKS 196              // ceil(NN/256)
#define DEG_BPS   3125                 // EE/256
#define GATH_T_BLOCKS 1563             // ceil(NN*8/256)
#define KK 96                          // FF + HH

// gate-GEMM (mma) config — R11 champion layout
#define NPB 128
#define GATE_BLOCKS 391                // ceil(NN/128)
#define BSH_W 72
#define HR_W  68
#define SMEM_GATES ((KK * BSH_W + 8 * 16 * HR_W) * 4)   // 62464 bytes

typedef unsigned long long u64;

// ---------------- scratch (device globals; no allocation allowed) ----------
__device__ __align__(16) float g_aggx[(size_t)TT * NN * FF];
__device__ __align__(16) float g_h   [(size_t)NN * HH];
__device__ int   g_deg [TOTN];
__device__ int   g_roff[TOTN];
__device__ int   g_cur [TOTN];
__device__ int   g_bsum[256];
__device__ u64   g_csrp[(size_t)TT * EE];   // packed (src, norm) per edge
__device__ float g_dinv[TOTN];

__device__ __align__(16) unsigned g_Wmma[3][KK][HH];
__device__ float g_bv[3][HH];

__device__ __forceinline__ float sigmoidf_(float x) {
    return 1.0f / (1.0f + __expf(-x));
}

__device__ __forceinline__ unsigned f2tf(float f) {
    unsigned r; asm("cvt.rna.tf32.f32 %0, %1;" : "=r"(r) : "f"(f)); return r;
}

__device__ __forceinline__ void mma8(float* d,
                                     unsigned a0, unsigned a1, unsigned a2, unsigned a3,
                                     unsigned b0, unsigned b1) {
    asm volatile("mma.sync.aligned.m16n8k8.row.col.f32.tf32.tf32.f32 "
        "{%0,%1,%2,%3}, {%4,%5,%6,%7}, {%8,%9}, {%0,%1,%2,%3};"
        : "+f"(d[0]), "+f"(d[1]), "+f"(d[2]), "+f"(d[3])
        : "r"(a0), "r"(a1), "r"(a2), "r"(a3), "r"(b0), "r"(b1));
}

// ---------------- prep / clears ---------------------------------------------

__global__ void k_clear_h() {
    unsigned idx = blockIdx.x * blockDim.x + threadIdx.x;
    if (idx < (unsigned)(NN * HH)) g_h[idx] = 0.0f;
}

__global__ void k_clear_t(int t) {     // clear deg/cur slice for timestep t
    unsigned i = blockIdx.x * blockDim.x + threadIdx.x;
    if (i < (unsigned)NN) { g_deg[t * NN + i] = 0; g_cur[t * NN + i] = 0; }
}

// one block per gate: build k-major tf32 weight panel + folded biases
__global__ void k_prep(const float* __restrict__ Wz, const float* __restrict__ bz,
                       const float* __restrict__ Wr, const float* __restrict__ br,
                       const float* __restrict__ Wh, const float* __restrict__ bh,
                       const float* __restrict__ Lz, const float* __restrict__ Lzb,
                       const float* __restrict__ Lr, const float* __restrict__ Lrb,
                       const float* __restrict__ Lh, const float* __restrict__ Lhb) {
    int g = blockIdx.x;
    int t = threadIdx.x;
    const float* W  = (g == 0) ? Wz  : (g == 1) ? Wr  : Wh;
    const float* b  = (g == 0) ? bz  : (g == 1) ? br  : bh;
    const float* L  = (g == 0) ? Lz  : (g == 1) ? Lr  : Lh;
    const float* Lb = (g == 0) ? Lzb : (g == 1) ? Lrb : Lhb;

    for (int e = t; e < KK * HH; e += 256) {
        int k = e >> 6, n = e & 63;
        float w;
        if (k < FF) {
            float s = 0.f;
            #pragma unroll 8
            for (int m = 0; m < HH; m++) s += __ldg(W + k * HH + m) * __ldg(L + m * HH + n);
            w = s;
        } else {
            w = __ldg(L + (k + 32) * HH + n);
        }
        g_Wmma[g][k][n] = f2tf(w);
    }
    if (t < HH) {
        float sb = __ldg(Lb + t);
        #pragma unroll 8
        for (int m = 0; m < HH; m++) sb += __ldg(b + m) * __ldg(L + m * HH + t);
        g_bv[g][t] = sb;
    }
}

// ---------------- per-timestep degree -----------------------------------------

__global__ void k_deg_t(const int* __restrict__ ei, int t) {
    unsigned e = blockIdx.x * 256 + threadIdx.x;
    int d = __ldg(ei + (size_t)t * 2 * EE + EE + e);
    atomicAdd(&g_deg[t * NN + d], 1);
}

// ---------------- per-timestep exclusive scan (+ dinv) ------------------------

__global__ void k_scan_block_t(int t) {
    __shared__ int sh[256];
    int tid = threadIdx.x;
    int li = blockIdx.x * 256 + tid;    // local node index
    int i = t * NN + li;
    int v = (li < NN) ? g_deg[i] : 0;
    if (li < NN) g_dinv[i] = rsqrtf((float)(v + 1));
    sh[tid] = v;
    __syncthreads();
    #pragma unroll
    for (int off = 1; off < 256; off <<= 1) {
        int tv = (tid >= off) ? sh[tid - off] : 0;
        __syncthreads();
        sh[tid] += tv;
        __syncthreads();
    }
    if (li < NN) g_roff[i] = sh[tid] - v;
    if (tid == 255) g_bsum[blockIdx.x] = sh[255];
}

__global__ void k_scan_aux_t(int t) {
    __shared__ int sh[256];
    int tid = threadIdx.x;
    int v = (tid < SCAN_T_BLOCKS) ? g_bsum[tid] : 0;
    sh[tid] = v;
    __syncthreads();
    #pragma unroll
    for (int off = 1; off < 256; off <<= 1) {
        int tv = (tid >= off) ? sh[tid - off] : 0;
        __syncthreads();
        sh[tid] += tv;
        __syncthreads();
    }
    // exclusive prefix + this timestep's CSR base (each t owns exactly EE slots)
    if (tid < SCAN_T_BLOCKS) g_bsum[tid] = sh[tid] - v + t * EE;
}

__global__ void k_scan_add_t(int t) {
    int li = blockIdx.x * 256 + threadIdx.x;
    if (li < NN) g_roff[t * NN + li] += g_bsum[blockIdx.x];
}

// ---------------- per-timestep CSR placement ----------------------------------

__global__ void k_place_t(const int* __restrict__ ei, int t) {
    unsigned e = blockIdx.x * 256 + threadIdx.x;
    const int* base = ei + (size_t)t * 2 * EE;
    int s = __ldg(base + e);
    int d = __ldg(base + EE + e);
    int i = t * NN + d;
    int pos = g_roff[i] + atomicAdd(&g_cur[i], 1);
    float w = __ldg(&g_dinv[t * NN + s]) * __ldg(&g_dinv[i]);
    g_csrp[pos] = (u64)(unsigned)s | ((u64)__float_as_uint(w) << 32);
}

// ---------------- pull-mode gather, one timestep ------------------------------

__global__ void k_gather_t(const float* __restrict__ xs, int t) {
    unsigned idx = blockIdx.x * 256 + threadIdx.x;   // < NN*8
    if (idx >= (unsigned)NN * 8u) return;
    unsigned node = idx >> 3;
    unsigned c    = idx & 7u;
    unsigned nf   = t * NN + node;
    const float* x = xs + (size_t)t * NN * FF;

    float dd = g_dinv[nf];
    float4 acc = __ldg(reinterpret_cast<const float4*>(x + (size_t)node * FF) + c);
    float d2 = dd * dd;
    acc.x *= d2; acc.y *= d2; acc.z *= d2; acc.w *= d2;

    int beg = g_roff[nf];
    int end = beg + g_deg[nf];
    for (int p = beg; p < end; p++) {
        u64 rec = __ldg(g_csrp + p);
        int s = (int)(unsigned)(rec & 0xffffffffULL);
        float ns = __uint_as_float((unsigned)(rec >> 32));
        float4 v = __ldg(reinterpret_cast<const float4*>(x + (size_t)s * FF) + c);
        acc.x = fmaf(v.x, ns, acc.x);
        acc.y = fmaf(v.y, ns, acc.y);
        acc.z = fmaf(v.z, ns, acc.z);
        acc.w = fmaf(v.w, ns, acc.w);
    }
    reinterpret_cast<float4*>(g_aggx + (size_t)nf * FF)[c] = acc;
}

// ---------------- GRU gates on tensor cores (R11 champion version) -----------

__global__ void __launch_bounds__(256) k_gates_mma(int t) {
    extern __shared__ unsigned smem_u[];
    unsigned* Bsh = smem_u;
    unsigned* HRw = smem_u + KK * BSH_W + (threadIdx.x >> 5) * (16 * HR_W);

    int tid = threadIdx.x;
    int lane = tid & 31;
    int g4 = lane >> 2, t4 = lane & 3;
    int warp = tid >> 5;

    const float* aggx_t = g_aggx + (size_t)t * NN * FF;

    int node0 = blockIdx.x * NPB + warp * 16;
    int r0 = node0 + g4;
    int r1 = r0 + 8;
    bool v0 = r0 < NN, v1 = r1 < NN;

    unsigned Aa[4][4];
    #pragma unroll
    for (int kk = 0; kk < 4; kk++) {
        int c0 = kk * 8 + t4, c1 = c0 + 4;
        Aa[kk][0] = f2tf(v0 ? __ldg(aggx_t + (size_t)r0 * FF + c0) : 0.f);
        Aa[kk][1] = f2tf(v1 ? __ldg(aggx_t + (size_t)r1 * FF + c0) : 0.f);
        Aa[kk][2] = f2tf(v0 ? __ldg(aggx_t + (size_t)r0 * FF + c1) : 0.f);
        Aa[kk][3] = f2tf(v1 ? __ldg(aggx_t + (size_t)r1 * FF + c1) : 0.f);
    }

    float Z[8][4];
    float acc[8][4];

    for (int gate = 0; gate < 3; gate++) {
        __syncthreads();
        const unsigned* Wg = &g_Wmma[gate][0][0];
        for (int i = tid; i < KK * HH / 2; i += 256) {
            int k = i >> 5, j = (i & 31) * 2;
            uint2 w = *reinterpret_cast<const uint2*>(Wg + k * HH + j);
            Bsh[k * BSH_W + j]     = w.x;
            Bsh[k * BSH_W + j + 1] = w.y;
        }
        __syncthreads();

        #pragma unroll
        for (int nt = 0; nt < 8; nt++)
            #pragma unroll
            for (int q = 0; q < 4; q++) acc[nt][q] = 0.f;

        #pragma unroll
        for (int kk = 0; kk < 12; kk++) {
            unsigned a0, a1, a2, a3;
            if (kk < 4) {
                a0 = Aa[kk][0]; a1 = Aa[kk][1]; a2 = Aa[kk][2]; a3 = Aa[kk][3];
            } else if (gate < 2) {
                int c0 = (kk - 4) * 8 + t4, c1 = c0 + 4;
                a0 = f2tf(v0 ? __ldg(g_h + (size_t)r0 * HH + c0) : 0.f);
                a1 = f2tf(v1 ? __ldg(g_h + (size_t)r1 * HH + c0) : 0.f);
                a2 = f2tf(v0 ? __ldg(g_h + (size_t)r0 * HH + c1) : 0.f);
                a3 = f2tf(v1 ? __ldg(g_h + (size_t)r1 * HH + c1) : 0.f);
            } else {
                int c0 = (kk - 4) * 8 + t4, c1 = c0 + 4;
                a0 = HRw[g4 * HR_W + c0];
                a1 = HRw[(g4 + 8) * HR_W + c0];
                a2 = HRw[g4 * HR_W + c1];
                a3 = HRw[(g4 + 8) * HR_W + c1];
            }
            #pragma unroll
            for (int nt = 0; nt < 8; nt++) {
                unsigned b0 = Bsh[(kk * 8 + t4) * BSH_W + nt * 8 + g4];
                unsigned b1 = Bsh[(kk * 8 + t4 + 4) * BSH_W + nt * 8 + g4];
                mma8(acc[nt], a0, a1, a2, a3, b0, b1);
            }
        }

        if (gate == 0) {
            #pragma unroll
            for (int nt = 0; nt < 8; nt++) {
                int col = nt * 8 + 2 * t4;
                float ba = __ldg(&g_bv[0][col]), bb = __ldg(&g_bv[0][col + 1]);
                Z[nt][0] = sigmoidf_(acc[nt][0] + ba);
                Z[nt][1] = sigmoidf_(acc[nt][1] + bb);
                Z[nt][2] = sigmoidf_(acc[nt][2] + ba);
                Z[nt][3] = sigmoidf_(acc[nt][3] + bb);
            }
        } else if (gate == 1) {
            #pragma unroll
            for (int nt = 0; nt < 8; nt++) {
                int col = nt * 8 + 2 * t4;
                float ba = __ldg(&g_bv[1][col]), bb = __ldg(&g_bv[1][col + 1]);
                float h00 = v0 ? g_h[(size_t)r0 * HH + col]     : 0.f;
                float h01 = v0 ? g_h[(size_t)r0 * HH + col + 1] : 0.f;
                float h10 = v1 ? g_h[(size_t)r1 * HH + col]     : 0.f;
                float h11 = v1 ? g_h[(size_t)r1 * HH + col + 1] : 0.f;
                HRw[g4 * HR_W + col]           = f2tf(h00 * sigmoidf_(acc[nt][0] + ba));
                HRw[g4 * HR_W + col + 1]       = f2tf(h01 * sigmoidf_(acc[nt][1] + bb));
                HRw[(g4 + 8) * HR_W + col]     = f2tf(h10 * sigmoidf_(acc[nt][2] + ba));
                HRw[(g4 + 8) * HR_W + col + 1] = f2tf(h11 * sigmoidf_(acc[nt][3] + bb));
            }
        } else {
            #pragma unroll
            for (int nt = 0; nt < 8; nt++) {
                int col = nt * 8 + 2 * t4;
                float ba = __ldg(&g_bv[2][col]), bb = __ldg(&g_bv[2][col + 1]);
                float Ht0 = tanhf(acc[nt][0] + ba);
                float Ht1 = tanhf(acc[nt][1] + bb);
                float Ht2 = tanhf(acc[nt][2] + ba);
                float Ht3 = tanhf(acc[nt][3] + bb);
                if (v0) {
                    float h00 = g_h[(size_t)r0 * HH + col];
                    float h01 = g_h[(size_t)r0 * HH + col + 1];
                    float o0 = Z[nt][0] * h00 + (1.f - Z[nt][0]) * Ht0;
                    float o1 = Z[nt][1] * h01 + (1.f - Z[nt][1]) * Ht1;
                    *reinterpret_cast<float2*>(g_h + (size_t)r0 * HH + col) = make_float2(o0, o1);
                }
                if (v1) {
                    float h10 = g_h[(size_t)r1 * HH + col];
                    float h11 = g_h[(size_t)r1 * HH + col + 1];
                    float o2 = Z[nt][2] * h10 + (1.f - Z[nt][2]) * Ht2;
                    float o3 = Z[nt][3] * h11 + (1.f - Z[nt][3]) * Ht3;
                    *reinterpret_cast<float2*>(g_h + (size_t)r1 * HH + col) = make_float2(o2, o3);
                }
            }
        }
    }
}

__global__ void k_out(const float* __restrict__ oW, const float* __restrict__ ob,
                      float* __restrict__ out) {
    unsigned idx = blockIdx.x * blockDim.x + threadIdx.x;
    if (idx >= (unsigned)(NN * OUTC)) return;
    int i = idx >> 4, j = idx & 15;
    const float* hr = g_h + (size_t)i * HH;
    float acc = __ldg(ob + j);
    #pragma unroll
    for (int k = 0; k < HH; k++) acc += hr[k] * __ldg(oW + k * OUTC + j);
    out[idx] = acc;
}

// ---------------- launch (per-timestep pipelined fork/join graph) -----------
extern "C" void kernel_launch(void* const* d_in, const int* in_sizes, int n_in,
                              void* d_out, int out_size) {
    const float* xs  = (const float*)d_in[0];
    const int*   ei  = (const int*)  d_in[1];
    const float* Wz  = (const float*)d_in[2];
    const float* bz  = (const float*)d_in[3];
    const float* Wr  = (const float*)d_in[4];
    const float* br  = (const float*)d_in[5];
    const float* Wh  = (const float*)d_in[6];
    const float* bh  = (const float*)d_in[7];
    const float* Lz  = (const float*)d_in[8];
    const float* Lzb = (const float*)d_in[9];
    const float* Lr  = (const float*)d_in[10];
    const float* Lrb = (const float*)d_in[11];
    const float* Lh  = (const float*)d_in[12];
    const float* Lhb = (const float*)d_in[13];
    const float* oW  = (const float*)d_in[14];
    const float* ob  = (const float*)d_in[15];
    float* out = (float*)d_out;

    static cudaStream_t sB = nullptr;
    static cudaEvent_t evStart = nullptr;
    static cudaEvent_t evG[TT] = {};
    static bool inited = false;
    if (!inited) {
        cudaStreamCreateWithFlags(&sB, cudaStreamNonBlocking);
        cudaEventCreateWithFlags(&evStart, cudaEventDisableTiming);
        for (int t = 0; t < TT; t++)
            cudaEventCreateWithFlags(&evG[t], cudaEventDisableTiming);
        cudaFuncSetAttribute(k_gates_mma, cudaFuncAttributeMaxDynamicSharedMemorySize,
                             SMEM_GATES);
        inited = true;
    }

    // fork stream B off the capture origin (default stream)
    cudaEventRecord(evStart, 0);
    cudaStreamWaitEvent(sB, evStart, 0);

    // stream B: per-timestep preprocessing pipelines, t=0 first
    for (int t = 0; t < TT; t++) {
        k_clear_t<<<SCAN_T_BLOCKS, 256, 0, sB>>>(t);
        k_deg_t<<<DEG_BPS, 256, 0, sB>>>(ei, t);
        k_scan_block_t<<<SCAN_T_BLOCKS, 256, 0, sB>>>(t);
        k_scan_aux_t<<<1, 256, 0, sB>>>(t);
        k_scan_add_t<<<SCAN_T_BLOCKS, 256, 0, sB>>>(t);
        k_place_t<<<DEG_BPS, 256, 0, sB>>>(ei, t);
        k_gather_t<<<GATH_T_BLOCKS, 256, 0, sB>>>(xs, t);
        cudaEventRecord(evG[t], sB);
    }

    // default stream: weight prep + h init, then gated recurrent chain
    k_prep<<<3, 256>>>(Wz, bz, Wr, br, Wh, bh, Lz, Lzb, Lr, Lrb, Lh, Lhb);
    k_clear_h<<<(NN * HH + 255) / 256, 256>>>();
    for (int t = 0; t < TT; t++) {
        cudaStreamWaitEvent(0, evG[t], 0);
        k_gates_mma<<<GATE_BLOCKS, 256, SMEM_GATES>>>(t);
    }

    k_out<<<(NN * OUTC + 255) / 256, 256>>>(oW, ob, out);
}

// round 16
// speedup vs baseline: 1.1136x; 1.1136x over previous
#include <cuda_runtime.h>
#include <cuda_fp16.h>
#include <math.h>

#define TT 6
#define NN 50000
#define EE 800000
#define FF 32
#define HH 64
#define OUTC 16

#define TOTN (TT * NN)                 // 300000
#define SCAN_BLOCKS 1172               // ceil(TOTN/256)
#define AUX_PER_THREAD 5               // 256*5 = 1280 >= 1172
#define DEG_BPS   3125                 // EE/256
#define PLACE_BPS 3125
#define GATH_T_BLOCKS 1563             // ceil(NN*8/256)
#define KK 96                          // FF + HH
#define KK2 48                         // KK/2 (half2-packed k pairs)

// gate-GEMM (fp16 mma m16n8k16) config
#define NPB 128
#define GATE_BLOCKS 391                // ceil(NN/128)
#define BSH_W 72                       // Bsh stride (uints): 72%32=8 -> conflict-free
#define HR2_W 36                       // HR half2 stride (uints): 36%32=4 -> conflict-free
#define SMEM_GATES ((KK2 * BSH_W + 8 * 16 * HR2_W) * 4)   // 32256 bytes

typedef unsigned long long u64;

// ---------------- scratch (device globals; no allocation allowed) ----------
__device__ __align__(16) float g_aggx[(size_t)TT * NN * FF];
__device__ __align__(16) float g_h   [(size_t)NN * HH];
__device__ int   g_deg [TOTN];
__device__ int   g_roff[TOTN];
__device__ int   g_cur [TOTN];
__device__ int   g_bsum[SCAN_BLOCKS];
__device__ u64   g_csrp[(size_t)TT * EE];   // packed (src, norm) per edge
__device__ float g_dinv[TOTN];

// folded weights, packed half2 along k: g_Wh2[g][k2][n] = {w(2k2,n), w(2k2+1,n)}
__device__ __align__(16) unsigned g_Wh2[3][KK2][HH];
__device__ float g_bv[3][HH];

__device__ __forceinline__ float sigmoidf_(float x) {
    return 1.0f / (1.0f + __expf(-x));
}

__device__ __forceinline__ unsigned pkh2(float a, float b) {
    __half2 h = __floats2half2_rn(a, b);
    return *reinterpret_cast<unsigned*>(&h);
}

__device__ __forceinline__ void mma16(float* d,
                                      unsigned a0, unsigned a1, unsigned a2, unsigned a3,
                                      unsigned b0, unsigned b1) {
    asm volatile("mma.sync.aligned.m16n8k16.row.col.f32.f16.f16.f32 "
        "{%0,%1,%2,%3}, {%4,%5,%6,%7}, {%8,%9}, {%0,%1,%2,%3};"
        : "+f"(d[0]), "+f"(d[1]), "+f"(d[2]), "+f"(d[3])
        : "r"(a0), "r"(a1), "r"(a2), "r"(a3), "r"(b0), "r"(b1));
}

// ---------------- prep / clears ---------------------------------------------

__global__ void k_clear_h() {
    unsigned idx = blockIdx.x * blockDim.x + threadIdx.x;
    if (idx < (unsigned)(NN * HH)) g_h[idx] = 0.0f;
}

__global__ void k_clear_int2() {
    unsigned i = blockIdx.x * blockDim.x + threadIdx.x;
    if (i < (unsigned)TOTN) { g_deg[i] = 0; g_cur[i] = 0; }
}

// one block per gate: build k2-packed fp16 weight panel + folded biases
__global__ void k_prep(const float* __restrict__ Wz, const float* __restrict__ bz,
                       const float* __restrict__ Wr, const float* __restrict__ br,
                       const float* __restrict__ Wh, const float* __restrict__ bh,
                       const float* __restrict__ Lz, const float* __restrict__ Lzb,
                       const float* __restrict__ Lr, const float* __restrict__ Lrb,
                       const float* __restrict__ Lh, const float* __restrict__ Lhb) {
    int g = blockIdx.x;
    int t = threadIdx.x;
    const float* W  = (g == 0) ? Wz  : (g == 1) ? Wr  : Wh;
    const float* b  = (g == 0) ? bz  : (g == 1) ? br  : bh;
    const float* L  = (g == 0) ? Lz  : (g == 1) ? Lr  : Lh;
    const float* Lb = (g == 0) ? Lzb : (g == 1) ? Lrb : Lhb;

    for (int e = t; e < KK2 * HH; e += 256) {
        int k2 = e >> 6, n = e & 63;
        float w[2];
        #pragma unroll
        for (int q = 0; q < 2; q++) {
            int k = 2 * k2 + q;
            if (k < FF) {
                float s = 0.f;
                #pragma unroll 8
                for (int m = 0; m < HH; m++) s += __ldg(W + k * HH + m) * __ldg(L + m * HH + n);
                w[q] = s;
            } else {
                w[q] = __ldg(L + (k + 32) * HH + n);   // L_bot row (k-FF)+HH
            }
        }
        g_Wh2[g][k2][n] = pkh2(w[0], w[1]);
    }
    if (t < HH) {
        float sb = __ldg(Lb + t);
        #pragma unroll 8
        for (int m = 0; m < HH; m++) sb += __ldg(b + m) * __ldg(L + m * HH + t);
        g_bv[g][t] = sb;
    }
}

// ---------------- degree ------------------------------------------------------

__global__ void k_deg_all(const int* __restrict__ ei) {
    int t = blockIdx.x / DEG_BPS;
    unsigned e = (blockIdx.x % DEG_BPS) * 256 + threadIdx.x;
    int d = __ldg(ei + (size_t)t * 2 * EE + EE + e);
    atomicAdd(&g_deg[t * NN + d], 1);
}

// ---------------- exclusive scan (+ dinv fused) -------------------------------

__global__ void k_scan_block() {
    __shared__ int sh[256];
    int tid = threadIdx.x;
    int i = blockIdx.x * 256 + tid;
    int v = (i < TOTN) ? g_deg[i] : 0;
    if (i < TOTN) g_dinv[i] = rsqrtf((float)(v + 1));
    sh[tid] = v;
    __syncthreads();
    #pragma unroll
    for (int off = 1; off < 256; off <<= 1) {
        int tv = (tid >= off) ? sh[tid - off] : 0;
        __syncthreads();
        sh[tid] += tv;
        __syncthreads();
    }
    if (i < TOTN) g_roff[i] = sh[tid] - v;
    if (tid == 255) g_bsum[blockIdx.x] = sh[255];
}

__global__ void k_scan_aux() {
    __shared__ int part[256];
    int tid = threadIdx.x;
    int start = tid * AUX_PER_THREAD;
    int loc[AUX_PER_THREAD];
    int vv [AUX_PER_THREAD];
    int sum = 0;
    #pragma unroll
    for (int j = 0; j < AUX_PER_THREAD; j++) {
        int idx = start + j;
        int v = (idx < SCAN_BLOCKS) ? g_bsum[idx] : 0;
        vv[j] = v;
        sum += v;
        loc[j] = sum;
    }
    part[tid] = sum;
    __syncthreads();
    #pragma unroll
    for (int off = 1; off < 256; off <<= 1) {
        int tv = (tid >= off) ? part[tid - off] : 0;
        __syncthreads();
        part[tid] += tv;
        __syncthreads();
    }
    int prev = (tid > 0) ? part[tid - 1] : 0;
    #pragma unroll
    for (int j = 0; j < AUX_PER_THREAD; j++) {
        int idx = start + j;
        if (idx < SCAN_BLOCKS) g_bsum[idx] = prev + loc[j] - vv[j];
    }
}

__global__ void k_scan_add() {
    int i = blockIdx.x * 256 + threadIdx.x;
    if (i < TOTN) g_roff[i] += g_bsum[blockIdx.x];
}

// ---------------- CSR placement (packed src + norm) -------------------------

__global__ void k_place(const int* __restrict__ ei) {
    int t = blockIdx.x / PLACE_BPS;
    unsigned e = (blockIdx.x % PLACE_BPS) * 256 + threadIdx.x;
    const int* base = ei + (size_t)t * 2 * EE;
    int s = __ldg(base + e);
    int d = __ldg(base + EE + e);
    int i = t * NN + d;
    int pos = g_roff[i] + atomicAdd(&g_cur[i], 1);
    float w = __ldg(&g_dinv[t * NN + s]) * __ldg(&g_dinv[i]);
    g_csrp[pos] = (u64)(unsigned)s | ((u64)__float_as_uint(w) << 32);
}

// ---------------- pull-mode gather, one timestep ------------------------------

__global__ void k_gather_t(const float* __restrict__ xs, int t) {
    unsigned idx = blockIdx.x * 256 + threadIdx.x;   // < NN*8
    if (idx >= (unsigned)NN * 8u) return;
    unsigned node = idx >> 3;
    unsigned c    = idx & 7u;
    unsigned nf   = t * NN + node;
    const float* x = xs + (size_t)t * NN * FF;

    float dd = g_dinv[nf];
    float4 acc = __ldg(reinterpret_cast<const float4*>(x + (size_t)node * FF) + c);
    float d2 = dd * dd;
    acc.x *= d2; acc.y *= d2; acc.z *= d2; acc.w *= d2;

    int beg = g_roff[nf];
    int end = beg + g_deg[nf];
    for (int p = beg; p < end; p++) {
        u64 rec = __ldg(g_csrp + p);
        int s = (int)(unsigned)(rec & 0xffffffffULL);
        float ns = __uint_as_float((unsigned)(rec >> 32));
        float4 v = __ldg(reinterpret_cast<const float4*>(x + (size_t)s * FF) + c);
        acc.x = fmaf(v.x, ns, acc.x);
        acc.y = fmaf(v.y, ns, acc.y);
        acc.z = fmaf(v.z, ns, acc.z);
        acc.w = fmaf(v.w, ns, acc.w);
    }
    reinterpret_cast<float4*>(g_aggx + (size_t)nf * FF)[c] = acc;
}

// ---------------- GRU gates on tensor cores (fp16 mma m16n8k16) -------------
// Block: 256 thr = 8 warps, 128 nodes. Warp: 16 nodes. 6 kk steps of k=16.

__global__ void __launch_bounds__(256) k_gates_mma(int t) {
    extern __shared__ unsigned smem_u[];
    unsigned* Bsh = smem_u;                                         // [KK2][BSH_W]
    unsigned* HRw = smem_u + KK2 * BSH_W + (threadIdx.x >> 5) * (16 * HR2_W);

    int tid = threadIdx.x;
    int lane = tid & 31;
    int g4 = lane >> 2, t4 = lane & 3;
    int warp = tid >> 5;

    const float* aggx_t = g_aggx + (size_t)t * NN * FF;

    int node0 = blockIdx.x * NPB + warp * 16;
    int r0 = node0 + g4;
    int r1 = r0 + 8;
    bool v0 = r0 < NN, v1 = r1 < NN;

    // resident aggx A-fragments (kk = 0,1 cover k=0..31)
    unsigned Aa[2][4];
    #pragma unroll
    for (int kk = 0; kk < 2; kk++) {
        int c0 = kk * 16 + 2 * t4;
        float2 p;
        p = v0 ? __ldg(reinterpret_cast<const float2*>(aggx_t + (size_t)r0 * FF + c0))
               : make_float2(0.f, 0.f);
        Aa[kk][0] = pkh2(p.x, p.y);
        p = v1 ? __ldg(reinterpret_cast<const float2*>(aggx_t + (size_t)r1 * FF + c0))
               : make_float2(0.f, 0.f);
        Aa[kk][1] = pkh2(p.x, p.y);
        p = v0 ? __ldg(reinterpret_cast<const float2*>(aggx_t + (size_t)r0 * FF + c0 + 8))
               : make_float2(0.f, 0.f);
        Aa[kk][2] = pkh2(p.x, p.y);
        p = v1 ? __ldg(reinterpret_cast<const float2*>(aggx_t + (size_t)r1 * FF + c0 + 8))
               : make_float2(0.f, 0.f);
        Aa[kk][3] = pkh2(p.x, p.y);
    }

    float Z[8][4];
    float acc[8][4];

    for (int gate = 0; gate < 3; gate++) {
        __syncthreads();                       // protect Bsh (and HRw ordering)
        const unsigned* Wg = &g_Wh2[gate][0][0];
        for (int i = tid; i < KK2 * HH / 2; i += 256) {
            int k2 = i >> 5, j = (i & 31) * 2;
            uint2 w = *reinterpret_cast<const uint2*>(Wg + k2 * HH + j);
            Bsh[k2 * BSH_W + j]     = w.x;
            Bsh[k2 * BSH_W + j + 1] = w.y;
        }
        __syncthreads();

        #pragma unroll
        for (int nt = 0; nt < 8; nt++)
            #pragma unroll
            for (int q = 0; q < 4; q++) acc[nt][q] = 0.f;

        #pragma unroll
        for (int kk = 0; kk < 6; kk++) {
            unsigned a0, a1, a2, a3;
            if (kk < 2) {
                a0 = Aa[kk][0]; a1 = Aa[kk][1]; a2 = Aa[kk][2]; a3 = Aa[kk][3];
            } else if (gate < 2) {
                int ch = (kk - 2) * 16 + 2 * t4;
                float2 p;
                p = v0 ? __ldg(reinterpret_cast<const float2*>(g_h + (size_t)r0 * HH + ch))
                       : make_float2(0.f, 0.f);
                a0 = pkh2(p.x, p.y);
                p = v1 ? __ldg(reinterpret_cast<const float2*>(g_h + (size_t)r1 * HH + ch))
                       : make_float2(0.f, 0.f);
                a1 = pkh2(p.x, p.y);
                p = v0 ? __ldg(reinterpret_cast<const float2*>(g_h + (size_t)r0 * HH + ch + 8))
                       : make_float2(0.f, 0.f);
                a2 = pkh2(p.x, p.y);
                p = v1 ? __ldg(reinterpret_cast<const float2*>(g_h + (size_t)r1 * HH + ch + 8))
                       : make_float2(0.f, 0.f);
                a3 = pkh2(p.x, p.y);
            } else {
                int c2 = (kk - 2) * 8 + t4;
                a0 = HRw[g4 * HR2_W + c2];
                a1 = HRw[(g4 + 8) * HR2_W + c2];
                a2 = HRw[g4 * HR2_W + c2 + 4];
                a3 = HRw[(g4 + 8) * HR2_W + c2 + 4];
            }
            #pragma unroll
            for (int nt = 0; nt < 8; nt++) {
                unsigned b0 = Bsh[(kk * 8 + t4) * BSH_W + nt * 8 + g4];
                unsigned b1 = Bsh[(kk * 8 + 4 + t4) * BSH_W + nt * 8 + g4];
                mma16(acc[nt], a0, a1, a2, a3, b0, b1);
            }
        }

        if (gate == 0) {
            #pragma unroll
            for (int nt = 0; nt < 8; nt++) {
                int col = nt * 8 + 2 * t4;
                float ba = __ldg(&g_bv[0][col]), bb = __ldg(&g_bv[0][col + 1]);
                Z[nt][0] = sigmoidf_(acc[nt][0] + ba);
                Z[nt][1] = sigmoidf_(acc[nt][1] + bb);
                Z[nt][2] = sigmoidf_(acc[nt][2] + ba);
                Z[nt][3] = sigmoidf_(acc[nt][3] + bb);
            }
        } else if (gate == 1) {
            #pragma unroll
            for (int nt = 0; nt < 8; nt++) {
                int col = nt * 8 + 2 * t4;
                float ba = __ldg(&g_bv[1][col]), bb = __ldg(&g_bv[1][col + 1]);
                float2 hv0 = v0 ? __ldg(reinterpret_cast<const float2*>(g_h + (size_t)r0 * HH + col))
                                : make_float2(0.f, 0.f);
                float2 hv1 = v1 ? __ldg(reinterpret_cast<const float2*>(g_h + (size_t)r1 * HH + col))
                                : make_float2(0.f, 0.f);
                HRw[g4 * HR2_W + nt * 4 + t4] =
                    pkh2(hv0.x * sigmoidf_(acc[nt][0] + ba),
                         hv0.y * sigmoidf_(acc[nt][1] + bb));
                HRw[(g4 + 8) * HR2_W + nt * 4 + t4] =
                    pkh2(hv1.x * sigmoidf_(acc[nt][2] + ba),
                         hv1.y * sigmoidf_(acc[nt][3] + bb));
            }
            __syncwarp();                  // HRw is warp-private
        } else {
            #pragma unroll
            for (int nt = 0; nt < 8; nt++) {
                int col = nt * 8 + 2 * t4;
                float ba = __ldg(&g_bv[2][col]), bb = __ldg(&g_bv[2][col + 1]);
                float Ht0 = tanhf(acc[nt][0] + ba);
                float Ht1 = tanhf(acc[nt][1] + bb);
                float Ht2 = tanhf(acc[nt][2] + ba);
                float Ht3 = tanhf(acc[nt][3] + bb);
                if (v0) {
                    float2 hv = __ldg(reinterpret_cast<const float2*>(g_h + (size_t)r0 * HH + col));
                    float o0 = Z[nt][0] * hv.x + (1.f - Z[nt][0]) * Ht0;
                    float o1 = Z[nt][1] * hv.y + (1.f - Z[nt][1]) * Ht1;
                    *reinterpret_cast<float2*>(g_h + (size_t)r0 * HH + col) = make_float2(o0, o1);
                }
                if (v1) {
                    float2 hv = __ldg(reinterpret_cast<const float2*>(g_h + (size_t)r1 * HH + col));
                    float o2 = Z[nt][2] * hv.x + (1.f - Z[nt][2]) * Ht2;
                    float o3 = Z[nt][3] * hv.y + (1.f - Z[nt][3]) * Ht3;
                    *reinterpret_cast<float2*>(g_h + (size_t)r1 * HH + col) = make_float2(o2, o3);
                }
            }
        }
    }
}

__global__ void k_out(const float* __restrict__ oW, const float* __restrict__ ob,
                      float* __restrict__ out) {
    unsigned idx = blockIdx.x * blockDim.x + threadIdx.x;
    if (idx >= (unsigned)(NN * OUTC)) return;
    int i = idx >> 4, j = idx & 15;
    const float* hr = g_h + (size_t)i * HH;
    float acc = __ldg(ob + j);
    #pragma unroll
    for (int k = 0; k < HH; k++) acc += hr[k] * __ldg(oW + k * OUTC + j);
    out[idx] = acc;
}

// ---------------- launch (R14 fork/join multi-stream graph) ------------------
extern "C" void kernel_launch(void* const* d_in, const int* in_sizes, int n_in,
                              void* d_out, int out_size) {
    const float* xs  = (const float*)d_in[0];
    const int*   ei  = (const int*)  d_in[1];
    const float* Wz  = (const float*)d_in[2];
    const float* bz  = (const float*)d_in[3];
    const float* Wr  = (const float*)d_in[4];
    const float* br  = (const float*)d_in[5];
    const float* Wh  = (const float*)d_in[6];
    const float* bh  = (const float*)d_in[7];
    const float* Lz  = (const float*)d_in[8];
    const float* Lzb = (const float*)d_in[9];
    const float* Lr  = (const float*)d_in[10];
    const float* Lrb = (const float*)d_in[11];
    const float* Lh  = (const float*)d_in[12];
    const float* Lhb = (const float*)d_in[13];
    const float* oW  = (const float*)d_in[14];
    const float* ob  = (const float*)d_in[15];
    float* out = (float*)d_out;

    static cudaStream_t sB = nullptr;
    static cudaEvent_t evStart = nullptr, evPre = nullptr, evPrep = nullptr;
    static cudaEvent_t evG[TT] = {};
    static bool inited = false;
    if (!inited) {
        cudaStreamCreateWithFlags(&sB, cudaStreamNonBlocking);
        cudaEventCreateWithFlags(&evStart, cudaEventDisableTiming);
        cudaEventCreateWithFlags(&evPre, cudaEventDisableTiming);
        cudaEventCreateWithFlags(&evPrep, cudaEventDisableTiming);
        for (int t = 0; t < TT; t++)
            cudaEventCreateWithFlags(&evG[t], cudaEventDisableTiming);
        cudaFuncSetAttribute(k_gates_mma, cudaFuncAttributeMaxDynamicSharedMemorySize,
                             SMEM_GATES);
        inited = true;
    }

    // fork stream B off the capture origin (default stream)
    cudaEventRecord(evStart, 0);
    cudaStreamWaitEvent(sB, evStart, 0);

    // stream B: weight prep (independent of edge pipeline)
    k_prep<<<3, 256, 0, sB>>>(Wz, bz, Wr, br, Wh, bh, Lz, Lzb, Lr, Lrb, Lh, Lhb);
    cudaEventRecord(evPrep, sB);

    // default stream: edge preprocessing chain (batched, all timesteps)
    k_clear_h<<<(NN * HH + 255) / 256, 256>>>();
    k_clear_int2<<<SCAN_BLOCKS, 256>>>();
    k_deg_all<<<TT * DEG_BPS, 256>>>(ei);
    k_scan_block<<<SCAN_BLOCKS, 256>>>();
    k_scan_aux<<<1, 256>>>();
    k_scan_add<<<SCAN_BLOCKS, 256>>>();
    k_place<<<TT * PLACE_BPS, 256>>>(ei);
    cudaEventRecord(evPre, 0);

    // stream B: per-timestep gathers
    cudaStreamWaitEvent(sB, evPre, 0);
    for (int t = 0; t < TT; t++) {
        k_gather_t<<<GATH_T_BLOCKS, 256, 0, sB>>>(xs, t);
        cudaEventRecord(evG[t], sB);
    }

    // default stream: recurrent gate chain, each step gated on its gather
    cudaStreamWaitEvent(0, evPrep, 0);
    for (int t = 0; t < TT; t++) {
        cudaStreamWaitEvent(0, evG[t], 0);
        k_gates_mma<<<GATE_BLOCKS, 256, SMEM_GATES>>>(t);
    }

    k_out<<<(NN * OUTC + 255) / 256, 256>>>(oW, ob, out);
}